// round 2
// baseline (speedup 1.0000x reference)
#include <cuda_runtime.h>

#define SEQ_LEN   2048
#define STATE_LEN 1024
#define N_POI     10000
#define EPS_VAL   1e-6f
#define THREADS   256
#define PER_T     (SEQ_LEN / THREADS)    // 8
#define ROW_VEC4  (N_POI / 4)            // 2500 float4 per row

__global__ __launch_bounds__(THREADS)
void attn_loc_kernel(const int* __restrict__ his,
                     const int* __restrict__ cur,
                     const float* __restrict__ mat,
                     float* __restrict__ out)
{
    __shared__ float srow[N_POI];            // 40000 B
    __shared__ float sred[THREADS / 32];

    const int row = blockIdx.x;
    const int tid = threadIdx.x;

    // Prefetch gather indices (L1/L2-resident, 8KB shared by all CTAs)
    int cidx[PER_T];
#pragma unroll
    for (int k = 0; k < PER_T; k++)
        cidx[k] = __ldg(his + tid + k * THREADS);

    // Stage the full matrix row into smem with coalesced float4 loads.
    // Row byte offset = cur*40000, 16B-aligned.
    const float4* __restrict__ mrow4 =
        (const float4*)(mat + (size_t)__ldg(cur + row) * N_POI);
    float4* __restrict__ srow4 = (float4*)srow;
#pragma unroll 10
    for (int i = tid; i < ROW_VEC4; i += THREADS)
        srow4[i] = __ldg(mrow4 + i);
    __syncthreads();

    // Phase 1: gather from smem, map to energies, local max
    float v[PER_T];
    float mx = -INFINITY;
#pragma unroll
    for (int k = 0; k < PER_T; k++) {
        const float d = srow[cidx[k]];
        const float e = (d != 0.0f) ? (1.0f / d) : EPS_VAL;
        v[k] = e;
        mx = fmaxf(mx, e);
    }

    // Block max reduction
#pragma unroll
    for (int o = 16; o; o >>= 1)
        mx = fmaxf(mx, __shfl_xor_sync(0xffffffffu, mx, o));
    if ((tid & 31) == 0) sred[tid >> 5] = mx;
    __syncthreads();
    float bmax = sred[0];
#pragma unroll
    for (int w = 1; w < THREADS / 32; w++) bmax = fmaxf(bmax, sred[w]);
    __syncthreads();

    // Phase 2: exp(e - max), local sum
    float sum = 0.0f;
#pragma unroll
    for (int k = 0; k < PER_T; k++) {
        const float e = __expf(v[k] - bmax);
        v[k] = e;
        sum += e;
    }

    // Block sum reduction
#pragma unroll
    for (int o = 16; o; o >>= 1)
        sum += __shfl_xor_sync(0xffffffffu, sum, o);
    if ((tid & 31) == 0) sred[tid >> 5] = sum;
    __syncthreads();
    float bsum = 0.0f;
#pragma unroll
    for (int w = 0; w < THREADS / 32; w++) bsum += sred[w];

    // Phase 3: normalize + coalesced store
    const float inv = 1.0f / bsum;
    float* __restrict__ orow = out + (size_t)row * SEQ_LEN;
#pragma unroll
    for (int k = 0; k < PER_T; k++)
        orow[tid + k * THREADS] = v[k] * inv;
}

extern "C" void kernel_launch(void* const* d_in, const int* in_sizes, int n_in,
                              void* d_out, int out_size)
{
    const int*   his = (const int*)d_in[0];
    const int*   cur = (const int*)d_in[1];
    const float* mat = (const float*)d_in[2];
    float*       out = (float*)d_out;

    attn_loc_kernel<<<STATE_LEN, THREADS>>>(his, cur, mat, out);
}